// round 7
// baseline (speedup 1.0000x reference)
#include <cuda_runtime.h>
#include <cstdint>

#define SEQ   2048
#define EMB   1024
#define NH    16
#define HD    64
#define NTOK  8192      // B*S
#define NBH   64        // B*H

// Scratch
__device__ float g_Q[(size_t)NTOK * EMB];
__device__ float g_K[(size_t)NTOK * EMB];
__device__ float g_V[(size_t)NTOK * EMB];
__device__ float g_C[(size_t)NTOK * EMB];
__device__ float g_X[(size_t)NTOK * EMB];          // tf32-rounded x
__device__ float g_W[(size_t)4 * EMB * EMB];       // tf32-rounded Wq,Wk,Wv,Wo

__device__ __forceinline__ uint32_t f2t(float x) {
    uint32_t r; asm("cvt.rna.tf32.f32 %0, %1;" : "=r"(r) : "f"(x)); return r;
}
__device__ __forceinline__ float f2tf(float x) { return __uint_as_float(f2t(x)); }

__device__ __forceinline__ void mma8(float* d, const uint32_t* a, const uint32_t* b) {
    asm volatile(
        "mma.sync.aligned.m16n8k8.row.col.f32.tf32.tf32.f32 "
        "{%0,%1,%2,%3}, {%4,%5,%6,%7}, {%8,%9}, {%0,%1,%2,%3};\n"
        : "+f"(d[0]), "+f"(d[1]), "+f"(d[2]), "+f"(d[3])
        : "r"(a[0]), "r"(a[1]), "r"(a[2]), "r"(a[3]), "r"(b[0]), "r"(b[1]));
}

// ===========================================================================
// Round x and W to tf32 (RNA) once; all later smem staging is raw copy.
// ===========================================================================
__global__ void round_inputs(
    const float4* __restrict__ x,
    const float4* __restrict__ wq, const float4* __restrict__ wk,
    const float4* __restrict__ wv, const float4* __restrict__ wo)
{
    const size_t NX = (size_t)NTOK * EMB / 4;
    const size_t NW = (size_t)EMB * EMB / 4;
    float4* X4 = (float4*)g_X;
    float4* W4 = (float4*)g_W;
    size_t stride = (size_t)gridDim.x * blockDim.x;
    for (size_t i = (size_t)blockIdx.x * blockDim.x + threadIdx.x;
         i < NX + 4 * NW; i += stride) {
        const float4* s; float4* d;
        if (i < NX) { s = x + i; d = X4 + i; }
        else {
            size_t j = i - NX;
            int w = (int)(j / NW);
            size_t o = j % NW;
            const float4* ws = (w == 0) ? wq : (w == 1) ? wk : (w == 2) ? wv : wo;
            s = ws + o; d = W4 + (size_t)w * NW + o;
        }
        float4 v = *s;
        float4 r;
        r.x = f2tf(v.x); r.y = f2tf(v.y); r.z = f2tf(v.z); r.w = f2tf(v.w);
        *d = r;
    }
}

// ===========================================================================
// TF32 GEMM (mma.sync): C[m,n] = sum_k A[m,k]*W[n,k] + bias[n]
// 128x128 CTA tile, BK=32, 256 thr, warps 2x4, warp tile 64x32.
// Row-major smem stride 36 (frag loads conflict-free: (4g+t) mod 32 distinct).
// Split-half staging: LDG h -> 2 ks compute -> STS h; one barrier per chunk.
// One row per thread (tid&127), tile select tid>>7 -> STS.128 conflict-free.
// ===========================================================================
#define G_STR        36
#define G_TILE_WORDS (128 * G_STR)            // 4608
#define G_STAGE      (2 * G_TILE_WORDS)       // A + B per buffer
#define GEMM_SMEM_BYTES (2 * G_STAGE * 4)     // 73728

__device__ __forceinline__ void g_ldg_half(
    float4 v[4], const float* rowptr, int k0, int h)
{
#pragma unroll
    for (int p = 0; p < 4; p++)
        v[p] = *(const float4*)(rowptr + k0 + h * 16 + 4 * p);
}

__device__ __forceinline__ void g_sts_half(
    uint32_t* tilebase, int r, int h, const float4 v[4])
{
#pragma unroll
    for (int p = 0; p < 4; p++)
        *(float4*)&tilebase[r * G_STR + h * 16 + 4 * p] = v[p];
}

__device__ __forceinline__ void g_compute_ks(
    const uint32_t* As, const uint32_t* Bs, int kk,
    int wm, int wn, int gid, int tq, float acc[4][4][4])
{
    uint32_t af[4][4], bf[4][2];
#pragma unroll
    for (int mt = 0; mt < 4; mt++) {
        const int m0 = wm * 64 + mt * 16;
        af[mt][0] = As[(m0 + gid    ) * G_STR + kk + tq];
        af[mt][1] = As[(m0 + gid + 8) * G_STR + kk + tq];
        af[mt][2] = As[(m0 + gid    ) * G_STR + kk + tq + 4];
        af[mt][3] = As[(m0 + gid + 8) * G_STR + kk + tq + 4];
    }
#pragma unroll
    for (int nt = 0; nt < 4; nt++) {
        const int n0 = wn * 32 + nt * 8;
        bf[nt][0] = Bs[(n0 + gid) * G_STR + kk + tq];
        bf[nt][1] = Bs[(n0 + gid) * G_STR + kk + tq + 4];
    }
#pragma unroll
    for (int mt = 0; mt < 4; mt++)
#pragma unroll
        for (int nt = 0; nt < 4; nt++)
            mma8(acc[mt][nt], af[mt], bf[nt]);
}

template<int TRANS_OUT>
__device__ __forceinline__ void gemm_body(
    const float* __restrict__ A, const float* __restrict__ W,
    const float* __restrict__ bias, float* __restrict__ Cout)
{
    extern __shared__ uint32_t smw[];
    const int tid  = threadIdx.x;
    const int warp = tid >> 5, lane = tid & 31;
    const int wm = warp >> 2, wn = warp & 3;
    const int gid = lane >> 2, tq = lane & 3;
    const int bm = blockIdx.y * 128, bn = blockIdx.x * 128;

    const int r   = tid & 127;
    const int isB = tid >> 7;
    const float* rowptr = isB ? (W + (size_t)(bn + r) * EMB)
                              : (A + (size_t)(bm + r) * EMB);
    uint32_t* mytile0 = smw + isB * G_TILE_WORDS;

    float acc[4][4][4];
#pragma unroll
    for (int i = 0; i < 4; i++)
#pragma unroll
        for (int j = 0; j < 4; j++)
#pragma unroll
            for (int v = 0; v < 4; v++) acc[i][j][v] = 0.f;

    float4 v[4];
    // prologue: chunk 0 into buffer 0
    g_ldg_half(v, rowptr, 0, 0);
    g_sts_half(mytile0, r, 0, v);
    g_ldg_half(v, rowptr, 0, 1);
    g_sts_half(mytile0, r, 1, v);
    __syncthreads();

    int buf = 0;
#pragma unroll 1
    for (int c = 1; c < EMB / 32; c++) {
        const int k0 = c * 32;
        const uint32_t* As = smw + buf * G_STAGE;
        const uint32_t* Bs = As + G_TILE_WORDS;
        uint32_t* nxt = smw + (buf ^ 1) * G_STAGE + isB * G_TILE_WORDS;

        g_ldg_half(v, rowptr, k0, 0);
        g_compute_ks(As, Bs, 0, wm, wn, gid, tq, acc);
        g_compute_ks(As, Bs, 8, wm, wn, gid, tq, acc);
        g_sts_half(nxt, r, 0, v);
        g_ldg_half(v, rowptr, k0, 1);
        g_compute_ks(As, Bs, 16, wm, wn, gid, tq, acc);
        g_compute_ks(As, Bs, 24, wm, wn, gid, tq, acc);
        g_sts_half(nxt, r, 1, v);
        __syncthreads();
        buf ^= 1;
    }
    {
        const uint32_t* As = smw + buf * G_STAGE;
        const uint32_t* Bs = As + G_TILE_WORDS;
        g_compute_ks(As, Bs, 0,  wm, wn, gid, tq, acc);
        g_compute_ks(As, Bs, 8,  wm, wn, gid, tq, acc);
        g_compute_ks(As, Bs, 16, wm, wn, gid, tq, acc);
        g_compute_ks(As, Bs, 24, wm, wn, gid, tq, acc);
    }

    // epilogue
#pragma unroll
    for (int mt = 0; mt < 4; mt++) {
#pragma unroll
        for (int nt = 0; nt < 4; nt++) {
            const int m_ = bm + wm * 64 + mt * 16 + gid;
            const int n_ = bn + wn * 32 + nt * 8 + 2 * tq;
            const float bz0 = bias[n_], bz1 = bias[n_ + 1];
            float c00 = acc[mt][nt][0] + bz0;
            float c01 = acc[mt][nt][1] + bz1;
            float c10 = acc[mt][nt][2] + bz0;
            float c11 = acc[mt][nt][3] + bz1;
            if (TRANS_OUT) {
                // Q/K/V consumed by tf32 MMAs downstream: round once here.
                c00 = f2tf(c00); c01 = f2tf(c01);
                c10 = f2tf(c10); c11 = f2tf(c11);
                const int b = m_ >> 11, s = m_ & (SEQ - 1);
                const int h = n_ >> 6,  d = n_ & 63;
                *(float2*)&Cout[((size_t)(b*NH+h)*SEQ + s) * HD + d]     = make_float2(c00, c01);
                *(float2*)&Cout[((size_t)(b*NH+h)*SEQ + s + 8) * HD + d] = make_float2(c10, c11);
            } else {
                *(float2*)&Cout[(size_t)m_ * EMB + n_]       = make_float2(c00, c01);
                *(float2*)&Cout[(size_t)(m_ + 8) * EMB + n_] = make_float2(c10, c11);
            }
        }
    }
}

__global__ void __launch_bounds__(256, 2) gemm_qkv(
    const float* __restrict__ A, const float* __restrict__ Wcat,
    const float* __restrict__ bq, const float* __restrict__ bk,
    const float* __restrict__ bv,
    float* __restrict__ Qo, float* __restrict__ Ko, float* __restrict__ Vo)
{
    const int z = blockIdx.z;
    const float* W = Wcat + (size_t)z * EMB * EMB;
    const float* b = (z == 0) ? bq : (z == 1) ? bk : bv;
    float* o = (z == 0) ? Qo : (z == 1) ? Ko : Vo;
    gemm_body<1>(A, W, b, o);
}

__global__ void __launch_bounds__(256, 2) gemm_o(
    const float* __restrict__ A, const float* __restrict__ W,
    const float* __restrict__ bias, float* __restrict__ out)
{
    gemm_body<0>(A, W, bias, out);
}

// ===========================================================================
// Fused attention, TF32 mma.sync, 512 threads (16 warps). Unchanged from R6.
//   Qs[128][68]   A-op of gemm1
//   Ks[2][128][68] B-op of gemm1 (double-buffered)
//   Vs[128][72]   B-op of gemm2 (k-major)
//   Ps[128][132]  A-op of gemm2
// ===========================================================================
#define Q_STR  68
#define K_STR  68
#define V_STR  72
#define P_STR  132
#define QS_OFF 0
#define KS_OFF (128 * Q_STR)
#define VS_OFF (KS_OFF + 2 * 128 * K_STR)
#define PS_OFF (VS_OFF + 128 * V_STR)
#define ATTN_SMEM_WORDS (PS_OFF + 128 * P_STR)   // 52224 words = 208896 B

__global__ void __launch_bounds__(512, 1) attn_tf32(
    const float* __restrict__ Q, const float* __restrict__ K,
    const float* __restrict__ V, float* __restrict__ Cctx)
{
    extern __shared__ uint32_t sm[];
    uint32_t* Qs = sm + QS_OFF;
    uint32_t* Vs = sm + VS_OFF;
    uint32_t* Ps = sm + PS_OFF;

    const int tid  = threadIdx.x;
    const int warp = tid >> 5, lane = tid & 31;
    const int gid  = lane >> 2, tq = lane & 3;
    const int wm1 = warp >> 2, wn1 = warp & 3;    // gemm1: 4x4, warp tile 32x32
    const int wm2 = warp >> 1, wn2 = warp & 1;    // gemm2: 8x2, warp tile 16x32
    const int bh = blockIdx.y;
    const int q0 = blockIdx.x * 128;

    const float* Qbh = Q + (size_t)bh * SEQ * HD;
    const float* Kbh = K + (size_t)bh * SEQ * HD;
    const float* Vbh = V + (size_t)bh * SEQ * HD;

    int srow[4], scol[4];
#pragma unroll
    for (int p = 0; p < 4; p++) {
        const int idx = tid + (p << 9);
        srow[p] = idx >> 4;
        scol[p] = (idx & 15) << 2;
    }

    // prologue: Q tile, K0 -> buf0, V0
#pragma unroll
    for (int p = 0; p < 4; p++) {
        const float4 qv = *(const float4*)(Qbh + (size_t)(q0 + srow[p]) * HD + scol[p]);
        const float4 kv = *(const float4*)(Kbh + (size_t)srow[p] * HD + scol[p]);
        const float4 vv = *(const float4*)(Vbh + (size_t)srow[p] * HD + scol[p]);
        *(float4*)&Qs[srow[p] * Q_STR + scol[p]]            = qv;
        *(float4*)&sm[KS_OFF + srow[p] * K_STR + scol[p]]   = kv;
        *(float4*)&Vs[srow[p] * V_STR + scol[p]]            = vv;
    }
    __syncthreads();

    float acc2[4][4];
#pragma unroll
    for (int j = 0; j < 4; j++)
#pragma unroll
        for (int v = 0; v < 4; v++) acc2[j][v] = 0.f;

#pragma unroll 1
    for (int kt = 0; kt < 16; kt++) {
        const int nk = (kt + 1 < 16) ? (kt + 1) : 15;

        float4 kreg[4], vreg[4];
#pragma unroll
        for (int p = 0; p < 4; p++) {
            kreg[p] = *(const float4*)(Kbh + (size_t)(nk * 128 + srow[p]) * HD + scol[p]);
            vreg[p] = *(const float4*)(Vbh + (size_t)(nk * 128 + srow[p]) * HD + scol[p]);
        }

        const uint32_t* Ks = sm + KS_OFF + (kt & 1) * 128 * K_STR;

        // gemm1: S[i][j] = sum_d Q[i][d] K[j][d]
        float acc1[2][4][4];
#pragma unroll
        for (int i = 0; i < 2; i++)
#pragma unroll
            for (int j = 0; j < 4; j++)
#pragma unroll
                for (int v = 0; v < 4; v++) acc1[i][j][v] = 0.f;

#pragma unroll
        for (int ks = 0; ks < 8; ks++) {
            const int kk = ks * 8;
            uint32_t af[2][4], bf[4][2];
#pragma unroll
            for (int mt = 0; mt < 2; mt++) {
                const int m0 = wm1 * 32 + mt * 16;
                af[mt][0] = Qs[(m0 + gid    ) * Q_STR + kk + tq];
                af[mt][1] = Qs[(m0 + gid + 8) * Q_STR + kk + tq];
                af[mt][2] = Qs[(m0 + gid    ) * Q_STR + kk + tq + 4];
                af[mt][3] = Qs[(m0 + gid + 8) * Q_STR + kk + tq + 4];
            }
#pragma unroll
            for (int nt = 0; nt < 4; nt++) {
                const int n0 = wn1 * 32 + nt * 8;
                bf[nt][0] = Ks[(n0 + gid) * K_STR + kk + tq];
                bf[nt][1] = Ks[(n0 + gid) * K_STR + kk + tq + 4];
            }
#pragma unroll
            for (int mt = 0; mt < 2; mt++)
#pragma unroll
                for (int nt = 0; nt < 4; nt++)
                    mma8(acc1[mt][nt], af[mt], bf[nt]);
        }

        // STS K(kt+1) into the other buffer
        {
            uint32_t* Kn = sm + KS_OFF + ((kt + 1) & 1) * 128 * K_STR;
#pragma unroll
            for (int p = 0; p < 4; p++)
                *(float4*)&Kn[srow[p] * K_STR + scol[p]] = kreg[p];
        }

        // softsign (1/sqrt(64) folded): p = s/(8+|s|) -> Ps[i][j] (tf32)
#pragma unroll
        for (int mt = 0; mt < 2; mt++) {
#pragma unroll
            for (int nt = 0; nt < 4; nt++) {
                const int row = wm1 * 32 + mt * 16 + gid;
                const int col = wn1 * 32 + nt * 8 + 2 * tq;
                float s0 = acc1[mt][nt][0], s1 = acc1[mt][nt][1];
                float s2 = acc1[mt][nt][2], s3 = acc1[mt][nt][3];
                uint2 p01 = make_uint2(f2t(__fdividef(s0, 8.f + fabsf(s0))),
                                       f2t(__fdividef(s1, 8.f + fabsf(s1))));
                uint2 p23 = make_uint2(f2t(__fdividef(s2, 8.f + fabsf(s2))),
                                       f2t(__fdividef(s3, 8.f + fabsf(s3))));
                *(uint2*)&Ps[(row    ) * P_STR + col] = p01;
                *(uint2*)&Ps[(row + 8) * P_STR + col] = p23;
            }
        }
        __syncthreads();   // syncA: P (and next K) visible; V still stable

        // gemm2: ctx[i][d] += sum_j P[i][j] V[j][d]
#pragma unroll
        for (int ks = 0; ks < 16; ks++) {
            const int kk = ks * 8;
            uint32_t af[4], bf[4][2];
            const int i0 = wm2 * 16;
            af[0] = Ps[(i0 + gid    ) * P_STR + kk + tq];
            af[1] = Ps[(i0 + gid + 8) * P_STR + kk + tq];
            af[2] = Ps[(i0 + gid    ) * P_STR + kk + tq + 4];
            af[3] = Ps[(i0 + gid + 8) * P_STR + kk + tq + 4];
#pragma unroll
            for (int nt = 0; nt < 4; nt++) {
                const int d0 = wn2 * 32 + nt * 8;
                bf[nt][0] = Vs[(kk + tq    ) * V_STR + d0 + gid];
                bf[nt][1] = Vs[(kk + tq + 4) * V_STR + d0 + gid];
            }
#pragma unroll
            for (int nt = 0; nt < 4; nt++)
                mma8(acc2[nt], af, bf[nt]);
        }
        __syncthreads();   // syncB: everyone done reading Vs / Ps

        // STS V(kt+1)
#pragma unroll
        for (int p = 0; p < 4; p++)
            *(float4*)&Vs[srow[p] * V_STR + scol[p]] = vreg[p];
    }

    // epilogue: ctx -> [token, E], tf32-rounded for the raw-copy output GEMM
    const int b = bh >> 4, h = bh & 15;
#pragma unroll
    for (int nt = 0; nt < 4; nt++) {
        const int i = wm2 * 16 + gid;
        const int d = wn2 * 32 + nt * 8 + 2 * tq;
        float* base0 = &Cctx[(size_t)(b * SEQ + q0 + i    ) * EMB + h * HD + d];
        float* base1 = &Cctx[(size_t)(b * SEQ + q0 + i + 8) * EMB + h * HD + d];
        *(float2*)base0 = make_float2(f2tf(acc2[nt][0]), f2tf(acc2[nt][1]));
        *(float2*)base1 = make_float2(f2tf(acc2[nt][2]), f2tf(acc2[nt][3]));
    }
}

// ===========================================================================
extern "C" void kernel_launch(void* const* d_in, const int* in_sizes, int n_in,
                              void* d_out, int out_size)
{
    (void)in_sizes; (void)n_in; (void)out_size;
    const float* x  = (const float*)d_in[0];
    const float* Wq = (const float*)d_in[1];
    const float* bq = (const float*)d_in[2];
    const float* Wk = (const float*)d_in[3];
    const float* bk = (const float*)d_in[4];
    const float* Wv = (const float*)d_in[5];
    const float* bv = (const float*)d_in[6];
    const float* Wo = (const float*)d_in[7];
    const float* bo = (const float*)d_in[8];
    float* out = (float*)d_out;

    float *Qp, *Kp, *Vp, *Cp, *Xp, *Wp;
    cudaGetSymbolAddress((void**)&Qp, g_Q);
    cudaGetSymbolAddress((void**)&Kp, g_K);
    cudaGetSymbolAddress((void**)&Vp, g_V);
    cudaGetSymbolAddress((void**)&Cp, g_C);
    cudaGetSymbolAddress((void**)&Xp, g_X);
    cudaGetSymbolAddress((void**)&Wp, g_W);

    round_inputs<<<2048, 256>>>((const float4*)x, (const float4*)Wq,
                                (const float4*)Wk, (const float4*)Wv,
                                (const float4*)Wo);

    cudaFuncSetAttribute(gemm_qkv, cudaFuncAttributeMaxDynamicSharedMemorySize,
                         GEMM_SMEM_BYTES);
    cudaFuncSetAttribute(gemm_o, cudaFuncAttributeMaxDynamicSharedMemorySize,
                         GEMM_SMEM_BYTES);

    gemm_qkv<<<dim3(EMB / 128, NTOK / 128, 3), 256, GEMM_SMEM_BYTES>>>(
        Xp, Wp, bq, bk, bv, Qp, Kp, Vp);

    const size_t attn_smem = (size_t)ATTN_SMEM_WORDS * sizeof(uint32_t);
    cudaFuncSetAttribute(attn_tf32, cudaFuncAttributeMaxDynamicSharedMemorySize,
                         (int)attn_smem);
    attn_tf32<<<dim3(SEQ / 128, NBH), 512, attn_smem>>>(Qp, Kp, Vp, Cp);

    gemm_o<<<dim3(EMB / 128, NTOK / 128), 256, GEMM_SMEM_BYTES>>>(
        Cp, Wp + (size_t)3 * EMB * EMB, bo, out);
}

// round 8
// speedup vs baseline: 2.1571x; 2.1571x over previous
#include <cuda_runtime.h>
#include <cuda_fp16.h>
#include <cstdint>

#define SEQ   2048
#define EMB   1024
#define NH    16
#define HD    64
#define NTOK  8192      // B*S
#define NBH   64        // B*H

// Scratch (all fp16 except none)
__device__ __half g_Q[(size_t)NTOK * EMB];          // [bh][s][d]
__device__ __half g_K[(size_t)NTOK * EMB];          // [bh][s][d]
__device__ __half g_V[(size_t)NTOK * EMB];          // [bh][d][s]  (transposed!)
__device__ __half g_C[(size_t)NTOK * EMB];          // [token][E]
__device__ __half g_X[(size_t)NTOK * EMB];          // fp16 x
__device__ __half g_W[(size_t)4 * EMB * EMB];       // fp16 Wq,Wk,Wv,Wo

__device__ __forceinline__ void mma16(float* d, const uint32_t* a, const uint32_t* b) {
    asm volatile(
        "mma.sync.aligned.m16n8k16.row.col.f32.f16.f16.f32 "
        "{%0,%1,%2,%3}, {%4,%5,%6,%7}, {%8,%9}, {%0,%1,%2,%3};\n"
        : "+f"(d[0]), "+f"(d[1]), "+f"(d[2]), "+f"(d[3])
        : "r"(a[0]), "r"(a[1]), "r"(a[2]), "r"(a[3]), "r"(b[0]), "r"(b[1]));
}

// ===========================================================================
// Convert x and all W to fp16 once.
// ===========================================================================
__global__ void round_inputs(
    const float4* __restrict__ x,
    const float4* __restrict__ wq, const float4* __restrict__ wk,
    const float4* __restrict__ wv, const float4* __restrict__ wo)
{
    const size_t NX = (size_t)NTOK * EMB / 8;    // 8-float groups
    const size_t NW = (size_t)EMB * EMB / 8;
    __half* X = g_X;
    __half* W = g_W;
    const size_t stride = (size_t)gridDim.x * blockDim.x;
    for (size_t g = (size_t)blockIdx.x * blockDim.x + threadIdx.x;
         g < NX + 4 * NW; g += stride) {
        const float4* s; __half* d;
        if (g < NX) { s = x + 2 * g; d = X + 8 * g; }
        else {
            size_t j = g - NX;
            int w = (int)(j / NW);
            size_t o = j % NW;
            const float4* ws = (w == 0) ? wq : (w == 1) ? wk : (w == 2) ? wv : wo;
            s = ws + 2 * o; d = W + (size_t)w * NW * 8 + 8 * o;
        }
        float4 v0 = s[0], v1 = s[1];
        __half h[8];
        h[0] = __float2half_rn(v0.x); h[1] = __float2half_rn(v0.y);
        h[2] = __float2half_rn(v0.z); h[3] = __float2half_rn(v0.w);
        h[4] = __float2half_rn(v1.x); h[5] = __float2half_rn(v1.y);
        h[6] = __float2half_rn(v1.z); h[7] = __float2half_rn(v1.w);
        *(uint4*)d = *(uint4*)h;
    }
}

// ===========================================================================
// FP16 GEMM (mma.sync m16n8k16): C[m,n] = sum_k A[m,k]*W[n,k] + bias[n]
// 128x128 CTA tile, BK=32 halves (64B/row), 256 thr, warps 2x4, warp 64x32.
// smem rows stride 40 halves (20 words): frag banks (20g+t) mod 32 distinct.
// R6-proven cadence: LDG chunk c+1 -> compute c -> STS c+1 -> sync.
// ===========================================================================
#define G_STRH 40                   // halves per row slot
#define G_STRW 20                   // words
#define G_TILEW (128 * G_STRW)      // 2560 words per tile

struct GemmSmem {
    uint32_t As[2][G_TILEW];
    uint32_t Bs[2][G_TILEW];
};

__device__ __forceinline__ void g_stage(
    uint32_t* As, uint32_t* Bs,
    const uint4& a0, const uint4& a1, const uint4& w0, const uint4& w1,
    int lrow, int c)
{
    *(uint4*)&As[lrow * G_STRW + c * 4]        = a0;
    *(uint4*)&As[(lrow + 64) * G_STRW + c * 4] = a1;
    *(uint4*)&Bs[lrow * G_STRW + c * 4]        = w0;
    *(uint4*)&Bs[(lrow + 64) * G_STRW + c * 4] = w1;
}

__device__ __forceinline__ void g_compute(
    const uint32_t* As, const uint32_t* Bs,
    int wm, int wn, int gid, int tq, float acc[4][4][4])
{
#pragma unroll
    for (int ks = 0; ks < 2; ks++) {
        const int kw = ks * 8;
        uint32_t af[4][4], bf[4][2];
#pragma unroll
        for (int mt = 0; mt < 4; mt++) {
            const int m0 = wm * 64 + mt * 16;
            af[mt][0] = As[(m0 + gid    ) * G_STRW + kw + tq];
            af[mt][1] = As[(m0 + gid + 8) * G_STRW + kw + tq];
            af[mt][2] = As[(m0 + gid    ) * G_STRW + kw + tq + 4];
            af[mt][3] = As[(m0 + gid + 8) * G_STRW + kw + tq + 4];
        }
#pragma unroll
        for (int nt = 0; nt < 4; nt++) {
            const int n0 = wn * 32 + nt * 8;
            bf[nt][0] = Bs[(n0 + gid) * G_STRW + kw + tq];
            bf[nt][1] = Bs[(n0 + gid) * G_STRW + kw + tq + 4];
        }
#pragma unroll
        for (int mt = 0; mt < 4; mt++)
#pragma unroll
            for (int nt = 0; nt < 4; nt++)
                mma16(acc[mt][nt], af[mt], bf[nt]);
    }
}

// OUT_MODE: 0 = fp32 [token][E] (final out), 1 = half [bh][s][d] (Q,K),
//           2 = half [bh][d][s] (V transposed)
template<int OUT_MODE, typename OutT>
__device__ __forceinline__ void gemm_body(
    const __half* __restrict__ A, const __half* __restrict__ W,
    const float* __restrict__ bias, OutT* __restrict__ Cout, GemmSmem& S)
{
    const int tid  = threadIdx.x;
    const int bm   = blockIdx.y * 128;
    const int bn   = blockIdx.x * 128;
    const int lrow = tid >> 2;          // 0..63
    const int c    = tid & 3;           // 16B chunk in 64B row
    const int warp = tid >> 5, lane = tid & 31;
    const int wm = warp >> 2, wn = warp & 3;
    const int gid = lane >> 2, tq = lane & 3;

    const __half* A0 = A + (size_t)(bm + lrow) * EMB + c * 8;
    const __half* A1 = A0 + (size_t)64 * EMB;
    const __half* W0 = W + (size_t)(bn + lrow) * EMB + c * 8;
    const __half* W1 = W0 + (size_t)64 * EMB;

    float acc[4][4][4];
#pragma unroll
    for (int i = 0; i < 4; i++)
#pragma unroll
        for (int j = 0; j < 4; j++)
#pragma unroll
            for (int v = 0; v < 4; v++) acc[i][j][v] = 0.f;

    uint4 a0 = *(const uint4*)(A0);
    uint4 a1 = *(const uint4*)(A1);
    uint4 w0 = *(const uint4*)(W0);
    uint4 w1 = *(const uint4*)(W1);
    g_stage(S.As[0], S.Bs[0], a0, a1, w0, w1, lrow, c);
    __syncthreads();

    int buf = 0;
#pragma unroll 1
    for (int k0 = 32; k0 < EMB; k0 += 32) {
        a0 = *(const uint4*)(A0 + k0);
        a1 = *(const uint4*)(A1 + k0);
        w0 = *(const uint4*)(W0 + k0);
        w1 = *(const uint4*)(W1 + k0);
        g_compute(S.As[buf], S.Bs[buf], wm, wn, gid, tq, acc);
        g_stage(S.As[buf ^ 1], S.Bs[buf ^ 1], a0, a1, w0, w1, lrow, c);
        __syncthreads();
        buf ^= 1;
    }
    g_compute(S.As[buf], S.Bs[buf], wm, wn, gid, tq, acc);

#pragma unroll
    for (int mt = 0; mt < 4; mt++) {
#pragma unroll
        for (int nt = 0; nt < 4; nt++) {
            const int m_ = bm + wm * 64 + mt * 16 + gid;
            const int n_ = bn + wn * 32 + nt * 8 + 2 * tq;
            const float bz0 = bias[n_], bz1 = bias[n_ + 1];
            const float c00 = acc[mt][nt][0] + bz0;
            const float c01 = acc[mt][nt][1] + bz1;
            const float c10 = acc[mt][nt][2] + bz0;
            const float c11 = acc[mt][nt][3] + bz1;
            if (OUT_MODE == 0) {
                float* o = (float*)Cout;
                *(float2*)&o[(size_t)m_ * EMB + n_]       = make_float2(c00, c01);
                *(float2*)&o[(size_t)(m_ + 8) * EMB + n_] = make_float2(c10, c11);
            } else if (OUT_MODE == 1) {
                __half* o = (__half*)Cout;
                const int b = m_ >> 11, s = m_ & (SEQ - 1);
                const int h = n_ >> 6,  d = n_ & 63;
                *(__half2*)&o[((size_t)(b*NH+h)*SEQ + s) * HD + d] =
                    __floats2half2_rn(c00, c01);
                *(__half2*)&o[((size_t)(b*NH+h)*SEQ + s + 8) * HD + d] =
                    __floats2half2_rn(c10, c11);
            } else {
                __half* o = (__half*)Cout;
                const int b = m_ >> 11, s = m_ & (SEQ - 1);
                const int h = n_ >> 6,  d = n_ & 63;
                const size_t base = ((size_t)(b*NH+h)*HD + d) * SEQ;
                o[base + s]            = __float2half_rn(c00);
                o[base + SEQ + s]      = __float2half_rn(c01);   // d+1
                o[base + s + 8]        = __float2half_rn(c10);
                o[base + SEQ + s + 8]  = __float2half_rn(c11);
            }
        }
    }
}

__global__ void __launch_bounds__(256, 2) gemm_qkv(
    const __half* __restrict__ A, const __half* __restrict__ Wcat,
    const float* __restrict__ bq, const float* __restrict__ bk,
    const float* __restrict__ bv,
    __half* __restrict__ Qo, __half* __restrict__ Ko, __half* __restrict__ Vo)
{
    __shared__ GemmSmem S;
    const int z = blockIdx.z;
    const __half* W = Wcat + (size_t)z * EMB * EMB;
    if (z == 0)      gemm_body<1>(A, W, bq, Qo, S);
    else if (z == 1) gemm_body<1>(A, W, bk, Ko, S);
    else             gemm_body<2>(A, W, bv, Vo, S);
}

__global__ void __launch_bounds__(256, 2) gemm_o(
    const __half* __restrict__ A, const __half* __restrict__ W,
    const float* __restrict__ bias, float* __restrict__ out)
{
    __shared__ GemmSmem S;
    gemm_body<0>(A, W, bias, out, S);
}

// ===========================================================================
// Fused attention, fp16 mma m16n8k16, 512 threads.
// XOR-swizzled smem (w ^= (row&7)<<2): conflict-free STS.128 + frag LDS.
//   Qs [128 i][32w]   Ks[2][128 j][32w]   Vt [64 d][64w]   Ps [128 i][64w]
// R6 cadence: LDG next K/V -> gemm1 -> STS K -> P -> sync -> gemm2 -> sync -> STS V
// ===========================================================================
#define AQ_OFF 0
#define AK_OFF (128 * 32)                 // 4096
#define AV_OFF (AK_OFF + 2 * 128 * 32)    // 12288
#define AP_OFF (AV_OFF + 64 * 64)         // 16384
#define A_SMEM_WORDS (AP_OFF + 128 * 64)  // 24576 words = 96KB

__device__ __forceinline__ int swz32(int row, int w) {
    return row * 32 + (w ^ ((row & 7) << 2));
}
__device__ __forceinline__ int swz64(int row, int w) {
    return row * 64 + (w ^ ((row & 7) << 2));
}

__global__ void __launch_bounds__(512, 1) attn_f16(
    const __half* __restrict__ Q, const __half* __restrict__ K,
    const __half* __restrict__ V, __half* __restrict__ Cctx)
{
    extern __shared__ uint32_t sm[];

    const int tid  = threadIdx.x;
    const int warp = tid >> 5, lane = tid & 31;
    const int gid  = lane >> 2, tq = lane & 3;
    const int wm1 = warp >> 2, wn1 = warp & 3;    // gemm1: 4x4, warp 32x32
    const int wm2 = warp >> 1, wn2 = warp & 1;    // gemm2: 8x2, warp 16x32
    const int bh = blockIdx.y;
    const int q0 = blockIdx.x * 128;

    const __half* Qbh = Q + (size_t)bh * SEQ * HD;
    const __half* Kbh = K + (size_t)bh * SEQ * HD;
    const __half* Vbh = V + (size_t)bh * HD * SEQ;   // [d][s]

    // staging coords: Q/K tiles: 128 rows x 8 chunks; V tile: 64 rows x 16
    int qkr[2], qkc[2], vr[2], vc[2];
#pragma unroll
    for (int p = 0; p < 2; p++) {
        const int idx = tid + (p << 9);
        qkr[p] = idx >> 3;  qkc[p] = idx & 7;
        vr[p]  = idx >> 4;  vc[p]  = idx & 15;
    }

    // prologue: Q, K0 -> buf0, V0
#pragma unroll
    for (int p = 0; p < 2; p++) {
        const uint4 qv = *(const uint4*)(Qbh + (size_t)(q0 + qkr[p]) * HD + qkc[p] * 8);
        const uint4 kv = *(const uint4*)(Kbh + (size_t)qkr[p] * HD + qkc[p] * 8);
        const uint4 vv = *(const uint4*)(Vbh + (size_t)vr[p] * SEQ + vc[p] * 8);
        *(uint4*)&sm[AQ_OFF + swz32(qkr[p], 4 * qkc[p])] = qv;
        *(uint4*)&sm[AK_OFF + swz32(qkr[p], 4 * qkc[p])] = kv;
        *(uint4*)&sm[AV_OFF + swz64(vr[p],  4 * vc[p])]  = vv;
    }
    __syncthreads();

    float acc2[4][4];
#pragma unroll
    for (int j = 0; j < 4; j++)
#pragma unroll
        for (int v = 0; v < 4; v++) acc2[j][v] = 0.f;

#pragma unroll 1
    for (int kt = 0; kt < 16; kt++) {
        const int nk = (kt + 1 < 16) ? (kt + 1) : 15;

        uint4 kreg[2], vreg[2];
#pragma unroll
        for (int p = 0; p < 2; p++) {
            kreg[p] = *(const uint4*)(Kbh + (size_t)(nk * 128 + qkr[p]) * HD + qkc[p] * 8);
            vreg[p] = *(const uint4*)(Vbh + (size_t)vr[p] * SEQ + nk * 128 + vc[p] * 8);
        }

        const uint32_t* Ks = sm + AK_OFF + (kt & 1) * (128 * 32);

        // gemm1: S[i][j] = sum_d Q[i][d] K[j][d]   (k = 64, 4 steps)
        float acc1[2][4][4];
#pragma unroll
        for (int i = 0; i < 2; i++)
#pragma unroll
            for (int j = 0; j < 4; j++)
#pragma unroll
                for (int v = 0; v < 4; v++) acc1[i][j][v] = 0.f;

#pragma unroll
        for (int ks = 0; ks < 4; ks++) {
            const int kw = ks * 8;
            uint32_t af[2][4], bf[4][2];
#pragma unroll
            for (int mt = 0; mt < 2; mt++) {
                const int m0 = wm1 * 32 + mt * 16;
                af[mt][0] = sm[AQ_OFF + swz32(m0 + gid,     kw + tq)];
                af[mt][1] = sm[AQ_OFF + swz32(m0 + gid + 8, kw + tq)];
                af[mt][2] = sm[AQ_OFF + swz32(m0 + gid,     kw + tq + 4)];
                af[mt][3] = sm[AQ_OFF + swz32(m0 + gid + 8, kw + tq + 4)];
            }
#pragma unroll
            for (int nt = 0; nt < 4; nt++) {
                const int n0 = wn1 * 32 + nt * 8;
                bf[nt][0] = Ks[swz32(n0 + gid, kw + tq)];
                bf[nt][1] = Ks[swz32(n0 + gid, kw + tq + 4)];
            }
#pragma unroll
            for (int mt = 0; mt < 2; mt++)
#pragma unroll
                for (int nt = 0; nt < 4; nt++)
                    mma16(acc1[mt][nt], af[mt], bf[nt]);
        }

        // STS K(kt+1) into the other buffer
        {
            uint32_t* Kn = sm + AK_OFF + ((kt + 1) & 1) * (128 * 32);
#pragma unroll
            for (int p = 0; p < 2; p++)
                *(uint4*)&Kn[swz32(qkr[p], 4 * qkc[p])] = kreg[p];
        }

        // softsign (1/8 folded): p = s/(8+|s|)  -> Ps half2
#pragma unroll
        for (int mt = 0; mt < 2; mt++) {
#pragma unroll
            for (int nt = 0; nt < 4; nt++) {
                const int row = wm1 * 32 + mt * 16 + gid;
                const int cw  = wn1 * 16 + nt * 4 + tq;
                const float s0 = acc1[mt][nt][0], s1 = acc1[mt][nt][1];
                const float s2 = acc1[mt][nt][2], s3 = acc1[mt][nt][3];
                *(__half2*)&sm[AP_OFF + swz64(row, cw)] =
                    __floats2half2_rn(__fdividef(s0, 8.f + fabsf(s0)),
                                      __fdividef(s1, 8.f + fabsf(s1)));
                *(__half2*)&sm[AP_OFF + swz64(row + 8, cw)] =
                    __floats2half2_rn(__fdividef(s2, 8.f + fabsf(s2)),
                                      __fdividef(s3, 8.f + fabsf(s3)));
            }
        }
        __syncthreads();   // syncA: P + next-K visible; V stable

        // gemm2: ctx[i][d] += sum_j P[i][j] V[j][d]   (k = 128, 8 steps)
#pragma unroll
        for (int ks = 0; ks < 8; ks++) {
            const int kw = ks * 8;
            uint32_t af[4], bf[4][2];
            const int i0 = wm2 * 16;
            af[0] = sm[AP_OFF + swz64(i0 + gid,     kw + tq)];
            af[1] = sm[AP_OFF + swz64(i0 + gid + 8, kw + tq)];
            af[2] = sm[AP_OFF + swz64(i0 + gid,     kw + tq + 4)];
            af[3] = sm[AP_OFF + swz64(i0 + gid + 8, kw + tq + 4)];
#pragma unroll
            for (int nt = 0; nt < 4; nt++) {
                const int d0 = wn2 * 32 + nt * 8;
                bf[nt][0] = sm[AV_OFF + swz64(d0 + gid, kw + tq)];
                bf[nt][1] = sm[AV_OFF + swz64(d0 + gid, kw + tq + 4)];
            }
#pragma unroll
            for (int nt = 0; nt < 4; nt++)
                mma16(acc2[nt], af, bf[nt]);
        }
        __syncthreads();   // syncB: done reading Vt / Ps

        // STS V(kt+1)
#pragma unroll
        for (int p = 0; p < 2; p++)
            *(uint4*)&sm[AV_OFF + swz64(vr[p], 4 * vc[p])] = vreg[p];
    }

    // epilogue: ctx -> half [token][E]
    const int b = bh >> 4, h = bh & 15;
#pragma unroll
    for (int nt = 0; nt < 4; nt++) {
        const int i = wm2 * 16 + gid;
        const int d = wn2 * 32 + nt * 8 + 2 * tq;
        __half* o0 = &Cctx[(size_t)(b * SEQ + q0 + i    ) * EMB + h * HD + d];
        __half* o1 = &Cctx[(size_t)(b * SEQ + q0 + i + 8) * EMB + h * HD + d];
        *(__half2*)o0 = __floats2half2_rn(acc2[nt][0], acc2[nt][1]);
        *(__half2*)o1 = __floats2half2_rn(acc2[nt][2], acc2[nt][3]);
    }
}

// ===========================================================================
extern "C" void kernel_launch(void* const* d_in, const int* in_sizes, int n_in,
                              void* d_out, int out_size)
{
    (void)in_sizes; (void)n_in; (void)out_size;
    const float* x  = (const float*)d_in[0];
    const float* Wq = (const float*)d_in[1];
    const float* bq = (const float*)d_in[2];
    const float* Wk = (const float*)d_in[3];
    const float* bk = (const float*)d_in[4];
    const float* Wv = (const float*)d_in[5];
    const float* bv = (const float*)d_in[6];
    const float* Wo = (const float*)d_in[7];
    const float* bo = (const float*)d_in[8];
    float* out = (float*)d_out;

    __half *Qp, *Kp, *Vp, *Cp, *Xp, *Wp;
    cudaGetSymbolAddress((void**)&Qp, g_Q);
    cudaGetSymbolAddress((void**)&Kp, g_K);
    cudaGetSymbolAddress((void**)&Vp, g_V);
    cudaGetSymbolAddress((void**)&Cp, g_C);
    cudaGetSymbolAddress((void**)&Xp, g_X);
    cudaGetSymbolAddress((void**)&Wp, g_W);

    round_inputs<<<2048, 256>>>((const float4*)x, (const float4*)Wq,
                                (const float4*)Wk, (const float4*)Wv,
                                (const float4*)Wo);

    gemm_qkv<<<dim3(EMB / 128, NTOK / 128, 3), 256>>>(
        Xp, Wp, bq, bk, bv, Qp, Kp, Vp);

    const size_t attn_smem = (size_t)A_SMEM_WORDS * sizeof(uint32_t);  // 96KB
    cudaFuncSetAttribute(attn_f16, cudaFuncAttributeMaxDynamicSharedMemorySize,
                         (int)attn_smem);
    attn_f16<<<dim3(SEQ / 128, NBH), 512, attn_smem>>>(Qp, Kp, Vp, Cp);

    gemm_o<<<dim3(EMB / 128, NTOK / 128), 256>>>(
        Cp, Wp + (size_t)3 * EMB * EMB, bo, out);
}

// round 9
// speedup vs baseline: 2.5273x; 1.1717x over previous
#include <cuda_runtime.h>
#include <cuda_fp16.h>
#include <cstdint>

#define SEQ   2048
#define EMB   1024
#define NH    16
#define HD    64
#define NTOK  8192      // B*S
#define NBH   64        // B*H

// Scratch
__device__ __half g_Q[(size_t)NTOK * EMB];          // [bh][s][d]
__device__ __half g_K[(size_t)NTOK * EMB];          // [bh][s][d]
__device__ __half g_V[(size_t)NTOK * EMB];          // [bh][d][s]  (transposed)
__device__ __half g_C[(size_t)NTOK * EMB];          // [token][E]
__device__ __half g_X[(size_t)NTOK * EMB];          // fp16 x
__device__ __half g_W[(size_t)4 * EMB * EMB];       // fp16 Wq,Wk,Wv,Wo

__device__ __forceinline__ void mma16(float* d, const uint32_t* a, const uint32_t* b) {
    asm volatile(
        "mma.sync.aligned.m16n8k16.row.col.f32.f16.f16.f32 "
        "{%0,%1,%2,%3}, {%4,%5,%6,%7}, {%8,%9}, {%0,%1,%2,%3};\n"
        : "+f"(d[0]), "+f"(d[1]), "+f"(d[2]), "+f"(d[3])
        : "r"(a[0]), "r"(a[1]), "r"(a[2]), "r"(a[3]), "r"(b[0]), "r"(b[1]));
}

__device__ __forceinline__ void ldsm_x4(
    uint32_t& r0, uint32_t& r1, uint32_t& r2, uint32_t& r3, uint32_t addr)
{
    asm volatile("ldmatrix.sync.aligned.m8n8.x4.shared.b16 {%0,%1,%2,%3}, [%4];"
                 : "=r"(r0), "=r"(r1), "=r"(r2), "=r"(r3) : "r"(addr));
}

__device__ __forceinline__ uint32_t smem_u32(const void* p) {
    uint32_t a;
    asm("{ .reg .u64 t; cvta.to.shared.u64 t, %1; cvt.u32.u64 %0, t; }"
        : "=r"(a) : "l"(p));
    return a;
}

// ===========================================================================
// Convert x and all W to fp16 once.
// ===========================================================================
__global__ void round_inputs(
    const float4* __restrict__ x,
    const float4* __restrict__ wq, const float4* __restrict__ wk,
    const float4* __restrict__ wv, const float4* __restrict__ wo)
{
    const size_t NX = (size_t)NTOK * EMB / 8;
    const size_t NW = (size_t)EMB * EMB / 8;
    __half* X = g_X;
    __half* W = g_W;
    const size_t stride = (size_t)gridDim.x * blockDim.x;
    for (size_t g = (size_t)blockIdx.x * blockDim.x + threadIdx.x;
         g < NX + 4 * NW; g += stride) {
        const float4* s; __half* d;
        if (g < NX) { s = x + 2 * g; d = X + 8 * g; }
        else {
            size_t j = g - NX;
            int w = (int)(j / NW);
            size_t o = j % NW;
            const float4* ws = (w == 0) ? wq : (w == 1) ? wk : (w == 2) ? wv : wo;
            s = ws + 2 * o; d = W + (size_t)w * NW * 8 + 8 * o;
        }
        float4 v0 = s[0], v1 = s[1];
        __half h[8];
        h[0] = __float2half_rn(v0.x); h[1] = __float2half_rn(v0.y);
        h[2] = __float2half_rn(v0.z); h[3] = __float2half_rn(v0.w);
        h[4] = __float2half_rn(v1.x); h[5] = __float2half_rn(v1.y);
        h[6] = __float2half_rn(v1.z); h[7] = __float2half_rn(v1.w);
        *(uint4*)d = *(uint4*)h;
    }
}

// ===========================================================================
// FP16 GEMM (mma m16n8k16 + ldmatrix): C[m,n] = sum_k A[m,k]*W[n,k] + bias[n]
// 128x128 CTA tile, BK=32 halves, 256 thr, warps 2x4, warp 64x32.
// smem rows stride 20 words; ldsm banks (20r mod 32) distinct for r=0..7.
// ===========================================================================
#define G_STRW 20                   // words per row slot
#define G_TILEW (128 * G_STRW)

struct GemmSmem {
    uint32_t As[2][G_TILEW];
    uint32_t Bs[2][G_TILEW];
};

__device__ __forceinline__ void g_stage(
    uint32_t* As, uint32_t* Bs,
    const uint4& a0, const uint4& a1, const uint4& w0, const uint4& w1,
    int lrow, int c)
{
    *(uint4*)&As[lrow * G_STRW + c * 4]        = a0;
    *(uint4*)&As[(lrow + 64) * G_STRW + c * 4] = a1;
    *(uint4*)&Bs[lrow * G_STRW + c * 4]        = w0;
    *(uint4*)&Bs[(lrow + 64) * G_STRW + c * 4] = w1;
}

// a0b/b0b: byte smem addrs incl lane offsets (row = tile0 + (lane&15), word = (lane>>4)*4)
__device__ __forceinline__ void g_compute(
    uint32_t a0b, uint32_t b0b, float acc[4][4][4])
{
#pragma unroll
    for (int ks = 0; ks < 2; ks++) {
        uint32_t af[4][4], bf[4][2];
#pragma unroll
        for (int mt = 0; mt < 4; mt++)
            ldsm_x4(af[mt][0], af[mt][1], af[mt][2], af[mt][3],
                    a0b + mt * (16 * G_STRW * 4) + ks * 32);
#pragma unroll
        for (int n2 = 0; n2 < 2; n2++) {
            uint32_t r0, r1, r2, r3;
            ldsm_x4(r0, r1, r2, r3, b0b + n2 * (16 * G_STRW * 4) + ks * 32);
            bf[2*n2][0] = r0; bf[2*n2+1][0] = r1;
            bf[2*n2][1] = r2; bf[2*n2+1][1] = r3;
        }
#pragma unroll
        for (int mt = 0; mt < 4; mt++)
#pragma unroll
            for (int nt = 0; nt < 4; nt++)
                mma16(acc[mt][nt], af[mt], bf[nt]);
    }
}

// OUT_MODE: 0 = fp32 [token][E], 1 = half [bh][s][d] (Q,K), 2 = half [bh][d][s] (V)
template<int OUT_MODE, typename OutT>
__device__ __forceinline__ void gemm_body(
    const __half* __restrict__ A, const __half* __restrict__ W,
    const float* __restrict__ bias, OutT* __restrict__ Cout, GemmSmem& S)
{
    const int tid  = threadIdx.x;
    const int bm   = blockIdx.y * 128;
    const int bn   = blockIdx.x * 128;
    const int lrow = tid >> 2;          // 0..63
    const int c    = tid & 3;
    const int warp = tid >> 5, lane = tid & 31;
    const int wm = warp >> 2, wn = warp & 3;
    const int gid = lane >> 2, tq = lane & 3;

    const __half* A0 = A + (size_t)(bm + lrow) * EMB + c * 8;
    const __half* A1 = A0 + (size_t)64 * EMB;
    const __half* W0 = W + (size_t)(bn + lrow) * EMB + c * 8;
    const __half* W1 = W0 + (size_t)64 * EMB;

    // ldmatrix lane addresses
    const int l16 = lane & 15;
    const int lhw = (lane >> 4) * 4;    // word offset 0 or 4
    const uint32_t aoff = (uint32_t)(((wm * 64 + l16) * G_STRW + lhw) * 4);
    const uint32_t boff = (uint32_t)(((wn * 32 + l16) * G_STRW + lhw) * 4);
    const uint32_t ab[2] = { smem_u32(&S.As[0][0]) + aoff, smem_u32(&S.As[1][0]) + aoff };
    const uint32_t bb[2] = { smem_u32(&S.Bs[0][0]) + boff, smem_u32(&S.Bs[1][0]) + boff };

    float acc[4][4][4];
#pragma unroll
    for (int i = 0; i < 4; i++)
#pragma unroll
        for (int j = 0; j < 4; j++)
#pragma unroll
            for (int v = 0; v < 4; v++) acc[i][j][v] = 0.f;

    uint4 a0 = *(const uint4*)(A0);
    uint4 a1 = *(const uint4*)(A1);
    uint4 w0 = *(const uint4*)(W0);
    uint4 w1 = *(const uint4*)(W1);
    g_stage(S.As[0], S.Bs[0], a0, a1, w0, w1, lrow, c);
    __syncthreads();

    int buf = 0;
#pragma unroll 1
    for (int k0 = 32; k0 < EMB; k0 += 32) {
        a0 = *(const uint4*)(A0 + k0);
        a1 = *(const uint4*)(A1 + k0);
        w0 = *(const uint4*)(W0 + k0);
        w1 = *(const uint4*)(W1 + k0);
        g_compute(ab[buf], bb[buf], acc);
        g_stage(S.As[buf ^ 1], S.Bs[buf ^ 1], a0, a1, w0, w1, lrow, c);
        __syncthreads();
        buf ^= 1;
    }
    g_compute(ab[buf], bb[buf], acc);

#pragma unroll
    for (int mt = 0; mt < 4; mt++) {
#pragma unroll
        for (int nt = 0; nt < 4; nt++) {
            const int m_ = bm + wm * 64 + mt * 16 + gid;
            const int n_ = bn + wn * 32 + nt * 8 + 2 * tq;
            const float bz0 = bias[n_], bz1 = bias[n_ + 1];
            const float c00 = acc[mt][nt][0] + bz0;
            const float c01 = acc[mt][nt][1] + bz1;
            const float c10 = acc[mt][nt][2] + bz0;
            const float c11 = acc[mt][nt][3] + bz1;
            if (OUT_MODE == 0) {
                float* o = (float*)Cout;
                *(float2*)&o[(size_t)m_ * EMB + n_]       = make_float2(c00, c01);
                *(float2*)&o[(size_t)(m_ + 8) * EMB + n_] = make_float2(c10, c11);
            } else if (OUT_MODE == 1) {
                __half* o = (__half*)Cout;
                const int b = m_ >> 11, s = m_ & (SEQ - 1);
                const int h = n_ >> 6,  d = n_ & 63;
                *(__half2*)&o[((size_t)(b*NH+h)*SEQ + s) * HD + d] =
                    __floats2half2_rn(c00, c01);
                *(__half2*)&o[((size_t)(b*NH+h)*SEQ + s + 8) * HD + d] =
                    __floats2half2_rn(c10, c11);
            } else {
                __half* o = (__half*)Cout;
                const int b = m_ >> 11, s = m_ & (SEQ - 1);
                const int h = n_ >> 6,  d = n_ & 63;
                const size_t base = ((size_t)(b*NH+h)*HD + d) * SEQ;
                o[base + s]            = __float2half_rn(c00);
                o[base + SEQ + s]      = __float2half_rn(c01);
                o[base + s + 8]        = __float2half_rn(c10);
                o[base + SEQ + s + 8]  = __float2half_rn(c11);
            }
        }
    }
}

__global__ void __launch_bounds__(256, 2) gemm_qkv(
    const __half* __restrict__ A, const __half* __restrict__ Wcat,
    const float* __restrict__ bq, const float* __restrict__ bk,
    const float* __restrict__ bv,
    __half* __restrict__ Qo, __half* __restrict__ Ko, __half* __restrict__ Vo)
{
    __shared__ GemmSmem S;
    const int z = blockIdx.z;
    const __half* W = Wcat + (size_t)z * EMB * EMB;
    if (z == 0)      gemm_body<1>(A, W, bq, Qo, S);
    else if (z == 1) gemm_body<1>(A, W, bk, Ko, S);
    else             gemm_body<2>(A, W, bv, Vo, S);
}

__global__ void __launch_bounds__(256, 2) gemm_o(
    const __half* __restrict__ A, const __half* __restrict__ W,
    const float* __restrict__ bias, float* __restrict__ out)
{
    __shared__ GemmSmem S;
    gemm_body<0>(A, W, bias, out, S);
}

// ===========================================================================
// Fused attention, fp16 mma + ldmatrix, 512 threads. XOR swizzle (R8-proven).
//   Qs [128 i][32w]   Ks[2][128 j][32w]   Vt [64 d][64w]   Ps [128 i][64w]
// ===========================================================================
#define AQ_OFF 0
#define AK_OFF (128 * 32)
#define AV_OFF (AK_OFF + 2 * 128 * 32)
#define AP_OFF (AV_OFF + 64 * 64)
#define A_SMEM_WORDS (AP_OFF + 128 * 64)  // 24576 words = 96KB

__device__ __forceinline__ int swz32(int row, int w) {
    return row * 32 + (w ^ ((row & 7) << 2));
}
__device__ __forceinline__ int swz64(int row, int w) {
    return row * 64 + (w ^ ((row & 7) << 2));
}
// byte address of 16B chunk at (row, word w) in a 32-words/row (128B) tile
__device__ __forceinline__ uint32_t a32(uint32_t base_b, int row, int w) {
    return base_b + row * 128 + (uint32_t)((w ^ ((row & 7) << 2)) << 2);
}
__device__ __forceinline__ uint32_t a64(uint32_t base_b, int row, int w) {
    return base_b + row * 256 + (uint32_t)((w ^ ((row & 7) << 2)) << 2);
}

__global__ void __launch_bounds__(512, 1) attn_f16(
    const __half* __restrict__ Q, const __half* __restrict__ K,
    const __half* __restrict__ V, __half* __restrict__ Cctx)
{
    extern __shared__ uint32_t sm[];
    const uint32_t smb = smem_u32(sm);

    const int tid  = threadIdx.x;
    const int warp = tid >> 5, lane = tid & 31;
    const int gid  = lane >> 2, tq = lane & 3;
    const int wm1 = warp >> 2, wn1 = warp & 3;    // gemm1: 4x4, warp 32x32
    const int wm2 = warp >> 1, wn2 = warp & 1;    // gemm2: 8x2, warp 16x32
    const int bh = blockIdx.y;
    const int q0 = blockIdx.x * 128;

    const __half* Qbh = Q + (size_t)bh * SEQ * HD;
    const __half* Kbh = K + (size_t)bh * SEQ * HD;
    const __half* Vbh = V + (size_t)bh * HD * SEQ;

    // ldmatrix lane coords
    const int l16 = lane & 15;
    const int lhw = (lane >> 4) * 4;

    // staging coords
    int qkr[2], qkc[2], vr[2], vc[2];
#pragma unroll
    for (int p = 0; p < 2; p++) {
        const int idx = tid + (p << 9);
        qkr[p] = idx >> 3;  qkc[p] = idx & 7;
        vr[p]  = idx >> 4;  vc[p]  = idx & 15;
    }

    // prologue: Q, K0 -> buf0, V0
#pragma unroll
    for (int p = 0; p < 2; p++) {
        const uint4 qv = *(const uint4*)(Qbh + (size_t)(q0 + qkr[p]) * HD + qkc[p] * 8);
        const uint4 kv = *(const uint4*)(Kbh + (size_t)qkr[p] * HD + qkc[p] * 8);
        const uint4 vv = *(const uint4*)(Vbh + (size_t)vr[p] * SEQ + vc[p] * 8);
        *(uint4*)&sm[AQ_OFF + swz32(qkr[p], 4 * qkc[p])] = qv;
        *(uint4*)&sm[AK_OFF + swz32(qkr[p], 4 * qkc[p])] = kv;
        *(uint4*)&sm[AV_OFF + swz64(vr[p],  4 * vc[p])]  = vv;
    }
    __syncthreads();

    float acc2[4][4];
#pragma unroll
    for (int j = 0; j < 4; j++)
#pragma unroll
        for (int v = 0; v < 4; v++) acc2[j][v] = 0.f;

#pragma unroll 1
    for (int kt = 0; kt < 16; kt++) {
        const int nk = (kt + 1 < 16) ? (kt + 1) : 15;

        uint4 kreg[2], vreg[2];
#pragma unroll
        for (int p = 0; p < 2; p++) {
            kreg[p] = *(const uint4*)(Kbh + (size_t)(nk * 128 + qkr[p]) * HD + qkc[p] * 8);
            vreg[p] = *(const uint4*)(Vbh + (size_t)vr[p] * SEQ + nk * 128 + vc[p] * 8);
        }

        const uint32_t ks_base = smb + (AK_OFF + (kt & 1) * (128 * 32)) * 4;

        // gemm1: S[i][j] = sum_d Q[i][d] K[j][d]   (4 k-steps of 16)
        float acc1[2][4][4];
#pragma unroll
        for (int i = 0; i < 2; i++)
#pragma unroll
            for (int j = 0; j < 4; j++)
#pragma unroll
                for (int v = 0; v < 4; v++) acc1[i][j][v] = 0.f;

#pragma unroll
        for (int ks = 0; ks < 4; ks++) {
            const int w = ks * 8 + lhw;
            uint32_t af[2][4], bf[4][2];
#pragma unroll
            for (int mt = 0; mt < 2; mt++) {
                const int row = wm1 * 32 + mt * 16 + l16;
                ldsm_x4(af[mt][0], af[mt][1], af[mt][2], af[mt][3],
                        a32(smb + AQ_OFF * 4, row, w));
            }
#pragma unroll
            for (int n2 = 0; n2 < 2; n2++) {
                const int row = wn1 * 32 + n2 * 16 + l16;
                uint32_t r0, r1, r2, r3;
                ldsm_x4(r0, r1, r2, r3, a32(ks_base, row, w));
                bf[2*n2][0] = r0; bf[2*n2+1][0] = r1;
                bf[2*n2][1] = r2; bf[2*n2+1][1] = r3;
            }
#pragma unroll
            for (int mt = 0; mt < 2; mt++)
#pragma unroll
                for (int nt = 0; nt < 4; nt++)
                    mma16(acc1[mt][nt], af[mt], bf[nt]);
        }

        // STS K(kt+1) into the other buffer
        {
            uint32_t* Kn = sm + AK_OFF + ((kt + 1) & 1) * (128 * 32);
#pragma unroll
            for (int p = 0; p < 2; p++)
                *(uint4*)&Kn[swz32(qkr[p], 4 * qkc[p])] = kreg[p];
        }

        // softsign (1/8 folded): p = s/(8+|s|) -> Ps half2
#pragma unroll
        for (int mt = 0; mt < 2; mt++) {
#pragma unroll
            for (int nt = 0; nt < 4; nt++) {
                const int row = wm1 * 32 + mt * 16 + gid;
                const int cw  = wn1 * 16 + nt * 4 + tq;
                const float s0 = acc1[mt][nt][0], s1 = acc1[mt][nt][1];
                const float s2 = acc1[mt][nt][2], s3 = acc1[mt][nt][3];
                *(__half2*)&sm[AP_OFF + swz64(row, cw)] =
                    __floats2half2_rn(__fdividef(s0, 8.f + fabsf(s0)),
                                      __fdividef(s1, 8.f + fabsf(s1)));
                *(__half2*)&sm[AP_OFF + swz64(row + 8, cw)] =
                    __floats2half2_rn(__fdividef(s2, 8.f + fabsf(s2)),
                                      __fdividef(s3, 8.f + fabsf(s3)));
            }
        }
        __syncthreads();   // syncA: P + next-K visible; V stable

        // gemm2: ctx[i][d] += sum_j P[i][j] V[j][d]  (8 k-steps of 16)
#pragma unroll
        for (int ks = 0; ks < 8; ks++) {
            const int w = ks * 8 + lhw;
            uint32_t af[4], bf[4][2];
            {
                const int row = wm2 * 16 + l16;
                ldsm_x4(af[0], af[1], af[2], af[3],
                        a64(smb + AP_OFF * 4, row, w));
            }
#pragma unroll
            for (int n2 = 0; n2 < 2; n2++) {
                const int row = wn2 * 32 + n2 * 16 + l16;
                uint32_t r0, r1, r2, r3;
                ldsm_x4(r0, r1, r2, r3, a64(smb + AV_OFF * 4, row, w));
                bf[2*n2][0] = r0; bf[2*n2+1][0] = r1;
                bf[2*n2][1] = r2; bf[2*n2+1][1] = r3;
            }
#pragma unroll
            for (int nt = 0; nt < 4; nt++)
                mma16(acc2[nt], af, bf[nt]);
        }
        __syncthreads();   // syncB: done reading Vt / Ps

        // STS V(kt+1)
#pragma unroll
        for (int p = 0; p < 2; p++)
            *(uint4*)&sm[AV_OFF + swz64(vr[p], 4 * vc[p])] = vreg[p];
    }

    // epilogue: ctx -> half [token][E]
    const int b = bh >> 4, h = bh & 15;
#pragma unroll
    for (int nt = 0; nt < 4; nt++) {
        const int i = wm2 * 16 + gid;
        const int d = wn2 * 32 + nt * 8 + 2 * tq;
        __half* o0 = &Cctx[(size_t)(b * SEQ + q0 + i    ) * EMB + h * HD + d];
        __half* o1 = &Cctx[(size_t)(b * SEQ + q0 + i + 8) * EMB + h * HD + d];
        *(__half2*)o0 = __floats2half2_rn(acc2[nt][0], acc2[nt][1]);
        *(__half2*)o1 = __floats2half2_rn(acc2[nt][2], acc2[nt][3]);
    }
}

// ===========================================================================
extern "C" void kernel_launch(void* const* d_in, const int* in_sizes, int n_in,
                              void* d_out, int out_size)
{
    (void)in_sizes; (void)n_in; (void)out_size;
    const float* x  = (const float*)d_in[0];
    const float* Wq = (const float*)d_in[1];
    const float* bq = (const float*)d_in[2];
    const float* Wk = (const float*)d_in[3];
    const float* bk = (const float*)d_in[4];
    const float* Wv = (const float*)d_in[5];
    const float* bv = (const float*)d_in[6];
    const float* Wo = (const float*)d_in[7];
    const float* bo = (const float*)d_in[8];
    float* out = (float*)d_out;

    __half *Qp, *Kp, *Vp, *Cp, *Xp, *Wp;
    cudaGetSymbolAddress((void**)&Qp, g_Q);
    cudaGetSymbolAddress((void**)&Kp, g_K);
    cudaGetSymbolAddress((void**)&Vp, g_V);
    cudaGetSymbolAddress((void**)&Cp, g_C);
    cudaGetSymbolAddress((void**)&Xp, g_X);
    cudaGetSymbolAddress((void**)&Wp, g_W);

    round_inputs<<<2048, 256>>>((const float4*)x, (const float4*)Wq,
                                (const float4*)Wk, (const float4*)Wv,
                                (const float4*)Wo);

    gemm_qkv<<<dim3(EMB / 128, NTOK / 128, 3), 256>>>(
        Xp, Wp, bq, bk, bv, Qp, Kp, Vp);

    const size_t attn_smem = (size_t)A_SMEM_WORDS * sizeof(uint32_t);  // 96KB
    cudaFuncSetAttribute(attn_f16, cudaFuncAttributeMaxDynamicSharedMemorySize,
                         (int)attn_smem);
    attn_f16<<<dim3(SEQ / 128, NBH), 512, attn_smem>>>(Qp, Kp, Vp, Cp);

    gemm_o<<<dim3(EMB / 128, NTOK / 128), 256>>>(
        Cp, Wp + (size_t)3 * EMB * EMB, bo, out);
}